// round 16
// baseline (speedup 1.0000x reference)
#include <cuda_runtime.h>
#include <cuda_fp16.h>
#include <math_constants.h>
#include <cstdint>

#define B_   2
#define L_   2048
#define E_   1024
#define H_   16
#define D_   64
#define DFF_ 4096
#define M_   (B_ * L_)   // 4096 tokens
#define HD_  (H_ * D_)   // 1024

// ---------------- scratch (device globals: allocation-guard safe) ----------------
__device__ float  g_x[M_ * E_];
__device__ __half g_h16[M_ * E_];
__device__ __half g_qkv16[(size_t)M_ * 3 * HD_];
__device__ __half g_ctx16[M_ * HD_];
__device__ __half g_gate16[(size_t)M_ * DFF_];
__device__ __half g_val16[(size_t)M_ * DFF_];
__device__ __half g_gg16[(size_t)M_ * DFF_];
__device__ __half g_wqkv16[(size_t)E_ * 3 * HD_];
__device__ __half g_wo16[(size_t)HD_ * E_];
__device__ __half g_ww16[(size_t)E_ * DFF_];
__device__ __half g_wv16[(size_t)E_ * DFF_];
__device__ __half g_wout16[(size_t)DFF_ * E_];

__device__ __forceinline__ uint32_t h2u(__half2 h) {
    return *reinterpret_cast<uint32_t*>(&h);
}

// ---------------- fused fp32->fp16 conversion for ALL 5 weight tensors ----------------
__global__ __launch_bounds__(256) void f2h_all_kernel(
    const float* __restrict__ s0, __half* __restrict__ d0,
    const float* __restrict__ s1, __half* __restrict__ d1,
    const float* __restrict__ s2, __half* __restrict__ d2,
    const float* __restrict__ s3, __half* __restrict__ d3,
    const float* __restrict__ s4, __half* __restrict__ d4) {
    unsigned i = blockIdx.x * 256 + threadIdx.x;
    const float* s; __half* d; unsigned off;
    if (i < 786432u)       { s = s0; d = d0; off = i; }
    else if (i < 1048576u) { s = s1; d = d1; off = i - 786432u; }
    else if (i < 2097152u) { s = s2; d = d2; off = i - 1048576u; }
    else if (i < 3145728u) { s = s3; d = d3; off = i - 2097152u; }
    else                   { s = s4; d = d4; off = i - 3145728u; }
    float4 v = ((const float4*)s)[off];
    ((uint2*)d)[off] = make_uint2(h2u(__floats2half2_rn(v.x, v.y)),
                                  h2u(__floats2half2_rn(v.z, v.w)));
}

// ---------------- rmsnorm (fp16 out) ----------------
__global__ __launch_bounds__(256) void rmsnorm_kernel(const float* __restrict__ x,
                                                      __half* __restrict__ y) {
    int row = blockIdx.x;
    float4 a = ((const float4*)(x + (size_t)row * E_))[threadIdx.x];
    float ss = a.x * a.x + a.y * a.y + a.z * a.z + a.w * a.w;
    __shared__ float red[8];
    __shared__ float sinv;
#pragma unroll
    for (int o = 16; o > 0; o >>= 1) ss += __shfl_xor_sync(0xffffffffu, ss, o);
    if ((threadIdx.x & 31) == 0) red[threadIdx.x >> 5] = ss;
    __syncthreads();
    if (threadIdx.x == 0) {
        float t = 0.f;
#pragma unroll
        for (int i = 0; i < 8; i++) t += red[i];
        sinv = rsqrtf(t * (1.0f / E_));
    }
    __syncthreads();
    float c = sinv;
    ((uint2*)(y + (size_t)row * E_))[threadIdx.x] =
        make_uint2(h2u(__floats2half2_rn(a.x * c, a.y * c)),
                   h2u(__floats2half2_rn(a.z * c, a.w * c)));
}

// ---------------- fused: x = x + rmsnorm(x); h16 = rmsnorm(x) ----------------
__global__ __launch_bounds__(256) void addnorm_kernel(float* __restrict__ x,
                                                      __half* __restrict__ h) {
    int row = blockIdx.x;
    float4 a = ((const float4*)(x + (size_t)row * E_))[threadIdx.x];
    __shared__ float red[8];
    __shared__ float sval;
    float ss = a.x * a.x + a.y * a.y + a.z * a.z + a.w * a.w;
#pragma unroll
    for (int o = 16; o > 0; o >>= 1) ss += __shfl_xor_sync(0xffffffffu, ss, o);
    if ((threadIdx.x & 31) == 0) red[threadIdx.x >> 5] = ss;
    __syncthreads();
    if (threadIdx.x == 0) {
        float t = 0.f;
#pragma unroll
        for (int i = 0; i < 8; i++) t += red[i];
        sval = 1.0f + rsqrtf(t * (1.0f / E_));
    }
    __syncthreads();
    float c = sval;
    a.x *= c; a.y *= c; a.z *= c; a.w *= c;
    float ss2 = a.x * a.x + a.y * a.y + a.z * a.z + a.w * a.w;
#pragma unroll
    for (int o = 16; o > 0; o >>= 1) ss2 += __shfl_xor_sync(0xffffffffu, ss2, o);
    if ((threadIdx.x & 31) == 0) red[threadIdx.x >> 5] = ss2;
    __syncthreads();
    if (threadIdx.x == 0) {
        float t = 0.f;
#pragma unroll
        for (int i = 0; i < 8; i++) t += red[i];
        sval = rsqrtf(t * (1.0f / E_));
    }
    __syncthreads();
    float inv2 = sval;
    ((float4*)(x + (size_t)row * E_))[threadIdx.x] = a;
    ((uint2*)(h + (size_t)row * E_))[threadIdx.x] =
        make_uint2(h2u(__floats2half2_rn(a.x * inv2, a.y * inv2)),
                   h2u(__floats2half2_rn(a.z * inv2, a.w * inv2)));
}

// ---------------- geglu (fp16 in/out) ----------------
__global__ __launch_bounds__(256) void geglu_kernel(const __half* __restrict__ g,
                                                    const __half* __restrict__ v,
                                                    __half* __restrict__ o) {
    int i = (blockIdx.x * 256 + threadIdx.x) * 4;
    uint2 gu = *(const uint2*)(g + i);
    uint2 vu = *(const uint2*)(v + i);
    float2 g0 = __half22float2(*reinterpret_cast<__half2*>(&gu.x));
    float2 g1 = __half22float2(*reinterpret_cast<__half2*>(&gu.y));
    float2 v0 = __half22float2(*reinterpret_cast<__half2*>(&vu.x));
    float2 v1 = __half22float2(*reinterpret_cast<__half2*>(&vu.y));
    float r0 = 0.5f * g0.x * (1.0f + erff(g0.x * 0.70710678118654752f)) * v0.x;
    float r1 = 0.5f * g0.y * (1.0f + erff(g0.y * 0.70710678118654752f)) * v0.y;
    float r2 = 0.5f * g1.x * (1.0f + erff(g1.x * 0.70710678118654752f)) * v1.x;
    float r3 = 0.5f * g1.y * (1.0f + erff(g1.y * 0.70710678118654752f)) * v1.y;
    *(uint2*)(o + i) = make_uint2(h2u(__floats2half2_rn(r0, r1)),
                                  h2u(__floats2half2_rn(r2, r3)));
}

// ================= mma helpers =================
__device__ __forceinline__ void mma_f16(float* d, const uint32_t* a, const uint32_t* b) {
    asm volatile(
        "mma.sync.aligned.m16n8k16.row.col.f32.f16.f16.f32 "
        "{%0,%1,%2,%3}, {%4,%5,%6,%7}, {%8,%9}, {%0,%1,%2,%3};\n"
        : "+f"(d[0]), "+f"(d[1]), "+f"(d[2]), "+f"(d[3])
        : "r"(a[0]), "r"(a[1]), "r"(a[2]), "r"(a[3]), "r"(b[0]), "r"(b[1]));
}

__device__ __forceinline__ void ldsm4(uint32_t* r, uint32_t saddr) {
    asm volatile("ldmatrix.sync.aligned.m8n8.x4.shared.b16 {%0,%1,%2,%3}, [%4];"
                 : "=r"(r[0]), "=r"(r[1]), "=r"(r[2]), "=r"(r[3]) : "r"(saddr));
}
__device__ __forceinline__ void ldsm4t(uint32_t* r, uint32_t saddr) {
    asm volatile("ldmatrix.sync.aligned.m8n8.x4.trans.shared.b16 {%0,%1,%2,%3}, [%4];"
                 : "=r"(r[0]), "=r"(r[1]), "=r"(r[2]), "=r"(r[3]) : "r"(saddr));
}
__device__ __forceinline__ void ldsm2t(uint32_t* r, uint32_t saddr) {
    asm volatile("ldmatrix.sync.aligned.m8n8.x2.trans.shared.b16 {%0,%1}, [%2];"
                 : "=r"(r[0]), "=r"(r[1]) : "r"(saddr));
}
__device__ __forceinline__ void ldsm2(uint32_t* r, uint32_t saddr) {
    asm volatile("ldmatrix.sync.aligned.m8n8.x2.shared.b16 {%0,%1}, [%2];"
                 : "=r"(r[0]), "=r"(r[1]) : "r"(saddr));
}

// ================= fp16 tensor-core GEMM (R14, unchanged) =================
#define BM 64
#define BN 128
#define BK 64
#define ASTR 72
#define BSTR 136
#define ATILE_H (BM * ASTR)
#define BTILE_H (BK * BSTR)
#define STAGE_H (ATILE_H + BTILE_H)
#define TG_SMEM (2 * STAGE_H * 2)   // 53248 B

__global__ __launch_bounds__(256, 3) void hgemm_kernel(
    int M, int N, int K,
    const __half* __restrict__ A, const __half* __restrict__ B,
    const float* __restrict__ bias, const float* __restrict__ res,
    float* __restrict__ C, __half* __restrict__ C16,
    const __half* __restrict__ B2, float* __restrict__ C2, __half* __restrict__ C216) {
    extern __shared__ __half sm[];

    if (blockIdx.z) { B = B2; C = C2; C16 = C216; }

    const int tid  = threadIdx.x;
    const int bm   = blockIdx.y * BM;
    const int bn   = blockIdx.x * BN;
    const int warp = tid >> 5, lane = tid & 31;
    const int wm   = (warp >> 2) * 32;
    const int wn   = (warp & 3) * 32;
    const int fr   = lane >> 2;
    const int fc   = lane & 3;
    const int arow_l = ((lane >> 3) & 1) * 8 + (lane & 7);
    const int acol_l = ((lane >> 4) & 1) * 8;
    const int brow4_l = ((lane >> 3) & 1) * 8 + (lane & 7);
    const int bcol4_l = ((lane >> 4) & 1) * 8;

    float acc[2][4][4];
#pragma unroll
    for (int i = 0; i < 2; i++)
#pragma unroll
        for (int j = 0; j < 4; j++)
#pragma unroll
            for (int k = 0; k < 4; k++) acc[i][j][k] = 0.f;

    auto fill = [&](int s, int kt) {
        __half* Ad = sm + s * STAGE_H;
        __half* Bd = Ad + ATILE_H;
#pragma unroll
        for (int p = 0; p < 2; p++) {
            int idx = p * 256 + tid;
            int row = idx >> 3, c8 = idx & 7;
            uint32_t dst = (uint32_t)__cvta_generic_to_shared(Ad + row * ASTR + c8 * 8);
            const __half* src = A + (size_t)(bm + row) * K + kt + c8 * 8;
            asm volatile("cp.async.cg.shared.global [%0], [%1], 16;\n" :: "r"(dst), "l"(src));
        }
#pragma unroll
        for (int p = 0; p < 4; p++) {
            int idx = p * 256 + tid;
            int row = idx >> 4, c16 = idx & 15;
            uint32_t dst = (uint32_t)__cvta_generic_to_shared(Bd + row * BSTR + c16 * 8);
            const __half* src = B + (size_t)(kt + row) * N + bn + c16 * 8;
            asm volatile("cp.async.cg.shared.global [%0], [%1], 16;\n" :: "r"(dst), "l"(src));
        }
        asm volatile("cp.async.commit_group;\n");
    };

    auto compute_tile = [&](int s) {
        const __half* Ab = sm + s * STAGE_H;
        const __half* Bb = Ab + ATILE_H;
        uint32_t abase = (uint32_t)__cvta_generic_to_shared(Ab + (wm + arow_l) * ASTR + acol_l);
        uint32_t bbase = (uint32_t)__cvta_generic_to_shared(Bb + brow4_l * BSTR + wn + bcol4_l);
#pragma unroll
        for (int ks = 0; ks < 4; ks++) {
            uint32_t af[2][4], bf[4][2];
#pragma unroll
            for (int mi = 0; mi < 2; mi++)
                ldsm4(af[mi], abase + (mi * 16 * ASTR + ks * 16) * 2);
#pragma unroll
            for (int n2 = 0; n2 < 2; n2++) {
                uint32_t r4[4];
                ldsm4t(r4, bbase + (ks * 16 * BSTR + n2 * 16) * 2);
                bf[2 * n2][0] = r4[0]; bf[2 * n2][1] = r4[1];
                bf[2 * n2 + 1][0] = r4[2]; bf[2 * n2 + 1][1] = r4[3];
            }
#pragma unroll
            for (int mi = 0; mi < 2; mi++)
#pragma unroll
                for (int ni = 0; ni < 4; ni++) mma_f16(acc[mi][ni], af[mi], bf[ni]);
        }
    };

    const int kiters = K / BK;
    fill(0, 0);
    asm volatile("cp.async.wait_group 0;\n");
    __syncthreads();

#pragma unroll 1
    for (int it = 0; it < kiters; ++it) {
        int cur = it & 1;
        if (it + 1 < kiters) fill(cur ^ 1, (it + 1) * BK);
        compute_tile(cur);
        asm volatile("cp.async.wait_group 0;\n");
        __syncthreads();
    }

#pragma unroll
    for (int mi = 0; mi < 2; mi++) {
#pragma unroll
        for (int ni = 0; ni < 4; ni++) {
            int gr = bm + wm + mi * 16 + fr;
            int gc = bn + wn + ni * 8 + fc * 2;
            float2 o0 = make_float2(acc[mi][ni][0], acc[mi][ni][1]);
            float2 o1 = make_float2(acc[mi][ni][2], acc[mi][ni][3]);
            if (bias) {
                float2 bv = *(const float2*)(bias + gc);
                o0.x += bv.x; o0.y += bv.y;
                o1.x += bv.x; o1.y += bv.y;
            }
            if (res) {
                float2 r0 = *(const float2*)(res + (size_t)gr * N + gc);
                float2 r1 = *(const float2*)(res + (size_t)(gr + 8) * N + gc);
                o0.x += r0.x; o0.y += r0.y;
                o1.x += r1.x; o1.y += r1.y;
            }
            if (C16) {
                *(__half2*)(C16 + (size_t)gr * N + gc) = __floats2half2_rn(o0.x, o0.y);
                *(__half2*)(C16 + (size_t)(gr + 8) * N + gc) = __floats2half2_rn(o1.x, o1.y);
            } else {
                *(float2*)(C + (size_t)gr * N + gc) = o0;
                *(float2*)(C + (size_t)(gr + 8) * N + gc) = o1;
            }
        }
    }
}

// ================= fp16 flash attention: 3-buffer KV ring, ONE barrier per tile =================
// Fill for tile kt+2 is issued AFTER the top barrier of iter kt: its target buffer
// (kt+2)%3 was last read in iter kt-1, which that barrier fences. No bottom barrier.
#define ATSTR 72
#define ATT_TILE_H (64 * ATSTR)
#define ATT_SMEM (7 * ATT_TILE_H * 2)   // Q + 3 x (K|V) = 64512 B

__global__ __launch_bounds__(128) void attn_kernel(const __half* __restrict__ qkv,
                                                   __half* __restrict__ ctx) {
    extern __shared__ __half smh[];
    __half* Qs = smh;
    __half* KV = Qs + ATT_TILE_H;

    const int qt = (int)(gridDim.x - 1 - blockIdx.x);   // longest rows first
    const int h = blockIdx.y, b = blockIdx.z;
    const int m0 = qt * 64;
    const int tid  = threadIdx.x;
    const int warp = tid >> 5, lane = tid & 31;
    const int fr = lane >> 2, fc = lane & 3;
    const int w16 = warp * 16;
    const int arow_l = ((lane >> 3) & 1) * 8 + (lane & 7);
    const int acol_l = ((lane >> 4) & 1) * 8;
    const int brow_l = arow_l;
    const int krow_l = lane & 7;
    const int ksel_l = ((lane >> 3) & 1) * 8;
    const float LOG2E = 1.44269504088896341f;
    const float slope2 = exp2f(-(1.0f + 7.0f * (float)h / 15.0f)) * LOG2E;
    const float step8 = 8.0f * slope2;
    const __half2 qscale = __floats2half2_rn(0.125f * LOG2E, 0.125f * LOG2E);

    auto fill_kv = [&](int kt) {
        __half* Kd = KV + (kt % 3) * 2 * ATT_TILE_H;
        __half* Vd = Kd + ATT_TILE_H;
        const int n0 = kt * 64;
#pragma unroll
        for (int p = 0; p < 4; p++) {
            int i = p * 128 + tid;
            int r = i >> 3, c = (i & 7) * 8;
            size_t base = ((size_t)(b * L_ + n0 + r) * H_ + h) * 3;
            uint32_t kd = (uint32_t)__cvta_generic_to_shared(Kd + r * ATSTR + c);
            uint32_t vd = (uint32_t)__cvta_generic_to_shared(Vd + r * ATSTR + c);
            const __half* ks = qkv + (base + 1) * D_ + c;
            const __half* vs = qkv + (base + 2) * D_ + c;
            asm volatile("cp.async.cg.shared.global [%0], [%1], 16;\n" :: "r"(kd), "l"(ks));
            asm volatile("cp.async.cg.shared.global [%0], [%1], 16;\n" :: "r"(vd), "l"(vs));
        }
        asm volatile("cp.async.commit_group;\n");
    };

    for (int i = tid; i < 64 * 16; i += 128) {
        int r = i >> 4, c = (i & 15) << 2;
        uint2 v = *(const uint2*)(qkv + ((((size_t)(b * L_ + m0 + r) * H_ + h) * 3 + 0) * D_ + c));
        __half2 q0 = __hmul2(*reinterpret_cast<__half2*>(&v.x), qscale);
        __half2 q1 = __hmul2(*reinterpret_cast<__half2*>(&v.y), qscale);
        *(uint2*)(Qs + r * ATSTR + c) = make_uint2(h2u(q0), h2u(q1));
    }
    fill_kv(0);
    if (qt >= 1) fill_kv(1);
    __syncthreads();

    const uint32_t qbase = (uint32_t)__cvta_generic_to_shared(Qs + (w16 + arow_l) * ATSTR + acol_l);

    uint32_t qf[4][4];
#pragma unroll
    for (int ks = 0; ks < 4; ks++) ldsm4(qf[ks], qbase + ks * 16 * 2);

    float oacc[8][4];
#pragma unroll
    for (int i = 0; i < 8; i++)
#pragma unroll
        for (int j = 0; j < 4; j++) oacc[i][j] = 0.f;
    float mrow0 = -CUDART_INF_F, mrow1 = -CUDART_INF_F;
    float lrow0 = 0.f, lrow1 = 0.f;

    const int gi0 = m0 + w16 + fr;
    const int gi1 = gi0 + 8;

#pragma unroll 1
    for (int kt = 0; kt <= qt; kt++) {
        const int n0 = kt * 64;
        // group for tile kt must complete; (kt<qt) means fill(kt+1) may stay pending
        if (kt < qt) asm volatile("cp.async.wait_group 1;\n");
        else         asm volatile("cp.async.wait_group 0;\n");
        __syncthreads();   // (a) fill kt visible, (b) iter kt-1 reads of buf (kt+2)%3 done
        if (kt + 2 <= qt) fill_kv(kt + 2);

        const __half* Kd = KV + (kt % 3) * 2 * ATT_TILE_H;
        const __half* Vd = Kd + ATT_TILE_H;
        const uint32_t kbase = (uint32_t)__cvta_generic_to_shared(Kd + krow_l * ATSTR + ksel_l);
        const uint32_t vbase = (uint32_t)__cvta_generic_to_shared(Vd + brow_l * ATSTR);

        float sacc[8][4];
#pragma unroll
        for (int i = 0; i < 8; i++)
#pragma unroll
            for (int j = 0; j < 4; j++) sacc[i][j] = 0.f;
#pragma unroll
        for (int ks = 0; ks < 4; ks++) {
            uint32_t bf[8][2];
#pragma unroll
            for (int ni = 0; ni < 8; ni++)
                ldsm2(bf[ni], kbase + (ni * 8 * ATSTR + ks * 16) * 2);
#pragma unroll
            for (int ni = 0; ni < 8; ni++) mma_f16(sacc[ni], qf[ks], bf[ni]);
        }

        {
            float a0 = slope2 * (float)(n0 + 2 * fc - gi0);
            float a2 = slope2 * (float)(n0 + 2 * fc - gi1);
            if (kt < qt) {
#pragma unroll
                for (int ni = 0; ni < 8; ni++) {
                    sacc[ni][0] += a0;
                    sacc[ni][1] += a0 + slope2;
                    sacc[ni][2] += a2;
                    sacc[ni][3] += a2 + slope2;
                    a0 += step8;
                    a2 += step8;
                }
            } else {
#pragma unroll
                for (int ni = 0; ni < 8; ni++) {
                    int gj = n0 + ni * 8 + 2 * fc;
                    sacc[ni][0] = (gj     > gi0) ? -CUDART_INF_F : sacc[ni][0] + a0;
                    sacc[ni][1] = (gj + 1 > gi0) ? -CUDART_INF_F : sacc[ni][1] + a0 + slope2;
                    sacc[ni][2] = (gj     > gi1) ? -CUDART_INF_F : sacc[ni][2] + a2;
                    sacc[ni][3] = (gj + 1 > gi1) ? -CUDART_INF_F : sacc[ni][3] + a2 + slope2;
                    a0 += step8;
                    a2 += step8;
                }
            }
        }

        float mx0 = -CUDART_INF_F, mx1 = -CUDART_INF_F;
#pragma unroll
        for (int ni = 0; ni < 8; ni++) {
            mx0 = fmaxf(mx0, fmaxf(sacc[ni][0], sacc[ni][1]));
            mx1 = fmaxf(mx1, fmaxf(sacc[ni][2], sacc[ni][3]));
        }
        mx0 = fmaxf(mx0, __shfl_xor_sync(0xffffffffu, mx0, 1));
        mx0 = fmaxf(mx0, __shfl_xor_sync(0xffffffffu, mx0, 2));
        mx1 = fmaxf(mx1, __shfl_xor_sync(0xffffffffu, mx1, 1));
        mx1 = fmaxf(mx1, __shfl_xor_sync(0xffffffffu, mx1, 2));
        float mn0 = fmaxf(mrow0, mx0);
        float mn1 = fmaxf(mrow1, mx1);
        float alpha0 = exp2f(mrow0 - mn0);
        float alpha1 = exp2f(mrow1 - mn1);
        float rs0 = 0.f, rs1 = 0.f;
#pragma unroll
        for (int ni = 0; ni < 8; ni++) {
            sacc[ni][0] = exp2f(sacc[ni][0] - mn0);
            sacc[ni][1] = exp2f(sacc[ni][1] - mn0);
            sacc[ni][2] = exp2f(sacc[ni][2] - mn1);
            sacc[ni][3] = exp2f(sacc[ni][3] - mn1);
            rs0 += sacc[ni][0] + sacc[ni][1];
            rs1 += sacc[ni][2] + sacc[ni][3];
        }
        rs0 += __shfl_xor_sync(0xffffffffu, rs0, 1);
        rs0 += __shfl_xor_sync(0xffffffffu, rs0, 2);
        rs1 += __shfl_xor_sync(0xffffffffu, rs1, 1);
        rs1 += __shfl_xor_sync(0xffffffffu, rs1, 2);
        lrow0 = lrow0 * alpha0 + rs0;
        lrow1 = lrow1 * alpha1 + rs1;
        mrow0 = mn0;
        mrow1 = mn1;
#pragma unroll
        for (int ni = 0; ni < 8; ni++) {
            oacc[ni][0] *= alpha0;
            oacc[ni][1] *= alpha0;
            oacc[ni][2] *= alpha1;
            oacc[ni][3] *= alpha1;
        }

#pragma unroll
        for (int ks = 0; ks < 4; ks++) {
            uint32_t af[4];
            af[0] = h2u(__floats2half2_rn(sacc[2 * ks][0],     sacc[2 * ks][1]));
            af[1] = h2u(__floats2half2_rn(sacc[2 * ks][2],     sacc[2 * ks][3]));
            af[2] = h2u(__floats2half2_rn(sacc[2 * ks + 1][0], sacc[2 * ks + 1][1]));
            af[3] = h2u(__floats2half2_rn(sacc[2 * ks + 1][2], sacc[2 * ks + 1][3]));
#pragma unroll
            for (int ni = 0; ni < 8; ni++) {
                uint32_t bf[2];
                ldsm2t(bf, vbase + (ks * 16 * ATSTR + ni * 8) * 2);
                mma_f16(oacc[ni], af, bf);
            }
        }
        // no bottom barrier: next iter's top barrier fences buffer reuse
    }

    float inv0 = 1.0f / lrow0;
    float inv1 = 1.0f / lrow1;
#pragma unroll
    for (int ni = 0; ni < 8; ni++) {
        int c = h * D_ + ni * 8 + 2 * fc;
        *(__half2*)(ctx + (size_t)(b * L_ + gi0) * HD_ + c) =
            __floats2half2_rn(oacc[ni][0] * inv0, oacc[ni][1] * inv0);
        *(__half2*)(ctx + (size_t)(b * L_ + gi1) * HD_ + c) =
            __floats2half2_rn(oacc[ni][2] * inv1, oacc[ni][3] * inv1);
    }
}

// ---------------- launch ----------------
extern "C" void kernel_launch(void* const* d_in, const int* in_sizes, int n_in,
                              void* d_out, int out_size) {
    (void)in_sizes; (void)n_in; (void)out_size;
    const float* X    = (const float*)d_in[0];
    const float* Wqkv = (const float*)d_in[2];
    const float* bqkv = (const float*)d_in[3];
    const float* Wo   = (const float*)d_in[4];
    const float* bo   = (const float*)d_in[5];
    const float* Ww   = (const float*)d_in[12];
    const float* Wv   = (const float*)d_in[13];
    const float* Wout = (const float*)d_in[14];
    float* out = (float*)d_out;

    float *x_p;
    __half *h16, *qkv16, *ctx16, *gate16, *val16, *gg16;
    __half *wqkv16, *wo16, *ww16, *wv16, *wout16;
    cudaGetSymbolAddress((void**)&x_p,    g_x);
    cudaGetSymbolAddress((void**)&h16,    g_h16);
    cudaGetSymbolAddress((void**)&qkv16,  g_qkv16);
    cudaGetSymbolAddress((void**)&ctx16,  g_ctx16);
    cudaGetSymbolAddress((void**)&gate16, g_gate16);
    cudaGetSymbolAddress((void**)&val16,  g_val16);
    cudaGetSymbolAddress((void**)&gg16,   g_gg16);
    cudaGetSymbolAddress((void**)&wqkv16, g_wqkv16);
    cudaGetSymbolAddress((void**)&wo16,   g_wo16);
    cudaGetSymbolAddress((void**)&ww16,   g_ww16);
    cudaGetSymbolAddress((void**)&wv16,   g_wv16);
    cudaGetSymbolAddress((void**)&wout16, g_wout16);

    cudaFuncSetAttribute(attn_kernel, cudaFuncAttributeMaxDynamicSharedMemorySize, ATT_SMEM);
    cudaFuncSetAttribute(hgemm_kernel, cudaFuncAttributeMaxDynamicSharedMemorySize, TG_SMEM);

    // 0. all fp16 weight conversions in one launch
    f2h_all_kernel<<<16384, 256>>>(Wqkv, wqkv16, Wo, wo16, Ww, ww16, Wv, wv16, Wout, wout16);

    // 1. h16 = rmsnorm(X)
    rmsnorm_kernel<<<M_, 256>>>(X, h16);
    // 2. qkv16 = h16 @ wqkv16 + bqkv
    hgemm_kernel<<<dim3(3 * HD_ / BN, M_ / BM), 256, TG_SMEM>>>(
        M_, 3 * HD_, E_, h16, wqkv16, bqkv, nullptr, nullptr, qkv16,
        nullptr, nullptr, nullptr);
    // 3. attention
    attn_kernel<<<dim3(L_ / 64, H_, B_), 128, ATT_SMEM>>>(qkv16, ctx16);
    // 4. x = X + ctx16 @ wo16 + bo
    hgemm_kernel<<<dim3(E_ / BN, M_ / BM), 256, TG_SMEM>>>(
        M_, E_, HD_, ctx16, wo16, bo, X, x_p, nullptr,
        nullptr, nullptr, nullptr);
    // 5+6. x = x + rmsnorm(x); h16 = rmsnorm(x)
    addnorm_kernel<<<M_, 256>>>(x_p, h16);
    // 7. gate16 / val16 (dual-output, z selects)
    hgemm_kernel<<<dim3(DFF_ / BN, M_ / BM, 2), 256, TG_SMEM>>>(
        M_, DFF_, E_, h16, ww16, nullptr, nullptr, nullptr, gate16,
        wv16, nullptr, val16);
    // 8. gg16 = gelu(gate16) * val16
    geglu_kernel<<<(M_ * DFF_) / 1024, 256>>>(gate16, val16, gg16);
    // 9. out = x + gg16 @ wout16
    hgemm_kernel<<<dim3(E_ / BN, M_ / BM), 256, TG_SMEM>>>(
        M_, E_, DFF_, gg16, wout16, nullptr, x_p, out, nullptr,
        nullptr, nullptr, nullptr);
}

// round 17
// speedup vs baseline: 1.0014x; 1.0014x over previous
#include <cuda_runtime.h>
#include <cuda_fp16.h>
#include <math_constants.h>
#include <cstdint>

#define B_   2
#define L_   2048
#define E_   1024
#define H_   16
#define D_   64
#define DFF_ 4096
#define M_   (B_ * L_)   // 4096 tokens
#define HD_  (H_ * D_)   // 1024

// ---------------- scratch (device globals: allocation-guard safe) ----------------
__device__ float  g_x[M_ * E_];
__device__ __half g_h16[M_ * E_];
__device__ __half g_qkv16[(size_t)M_ * 3 * HD_];
__device__ __half g_ctx16[M_ * HD_];
__device__ __half g_gate16[(size_t)M_ * DFF_];
__device__ __half g_val16[(size_t)M_ * DFF_];
__device__ __half g_gg16[(size_t)M_ * DFF_];
__device__ __half g_wqkv16[(size_t)E_ * 3 * HD_];
__device__ __half g_wo16[(size_t)HD_ * E_];
__device__ __half g_ww16[(size_t)E_ * DFF_];
__device__ __half g_wv16[(size_t)E_ * DFF_];
__device__ __half g_wout16[(size_t)DFF_ * E_];

__device__ __forceinline__ uint32_t h2u(__half2 h) {
    return *reinterpret_cast<uint32_t*>(&h);
}

// ---------------- fused fp32->fp16 conversion for ALL 5 weight tensors ----------------
__global__ __launch_bounds__(256) void f2h_all_kernel(
    const float* __restrict__ s0, __half* __restrict__ d0,
    const float* __restrict__ s1, __half* __restrict__ d1,
    const float* __restrict__ s2, __half* __restrict__ d2,
    const float* __restrict__ s3, __half* __restrict__ d3,
    const float* __restrict__ s4, __half* __restrict__ d4) {
    unsigned i = blockIdx.x * 256 + threadIdx.x;
    const float* s; __half* d; unsigned off;
    if (i < 786432u)       { s = s0; d = d0; off = i; }
    else if (i < 1048576u) { s = s1; d = d1; off = i - 786432u; }
    else if (i < 2097152u) { s = s2; d = d2; off = i - 1048576u; }
    else if (i < 3145728u) { s = s3; d = d3; off = i - 2097152u; }
    else                   { s = s4; d = d4; off = i - 3145728u; }
    float4 v = ((const float4*)s)[off];
    ((uint2*)d)[off] = make_uint2(h2u(__floats2half2_rn(v.x, v.y)),
                                  h2u(__floats2half2_rn(v.z, v.w)));
}

// ---------------- rmsnorm (fp16 out) ----------------
__global__ __launch_bounds__(256) void rmsnorm_kernel(const float* __restrict__ x,
                                                      __half* __restrict__ y) {
    int row = blockIdx.x;
    float4 a = ((const float4*)(x + (size_t)row * E_))[threadIdx.x];
    float ss = a.x * a.x + a.y * a.y + a.z * a.z + a.w * a.w;
    __shared__ float red[8];
    __shared__ float sinv;
#pragma unroll
    for (int o = 16; o > 0; o >>= 1) ss += __shfl_xor_sync(0xffffffffu, ss, o);
    if ((threadIdx.x & 31) == 0) red[threadIdx.x >> 5] = ss;
    __syncthreads();
    if (threadIdx.x == 0) {
        float t = 0.f;
#pragma unroll
        for (int i = 0; i < 8; i++) t += red[i];
        sinv = rsqrtf(t * (1.0f / E_));
    }
    __syncthreads();
    float c = sinv;
    ((uint2*)(y + (size_t)row * E_))[threadIdx.x] =
        make_uint2(h2u(__floats2half2_rn(a.x * c, a.y * c)),
                   h2u(__floats2half2_rn(a.z * c, a.w * c)));
}

// ---------------- fused: x = x + rmsnorm(x); h16 = rmsnorm(x) ----------------
__global__ __launch_bounds__(256) void addnorm_kernel(float* __restrict__ x,
                                                      __half* __restrict__ h) {
    int row = blockIdx.x;
    float4 a = ((const float4*)(x + (size_t)row * E_))[threadIdx.x];
    __shared__ float red[8];
    __shared__ float sval;
    float ss = a.x * a.x + a.y * a.y + a.z * a.z + a.w * a.w;
#pragma unroll
    for (int o = 16; o > 0; o >>= 1) ss += __shfl_xor_sync(0xffffffffu, ss, o);
    if ((threadIdx.x & 31) == 0) red[threadIdx.x >> 5] = ss;
    __syncthreads();
    if (threadIdx.x == 0) {
        float t = 0.f;
#pragma unroll
        for (int i = 0; i < 8; i++) t += red[i];
        sval = 1.0f + rsqrtf(t * (1.0f / E_));
    }
    __syncthreads();
    float c = sval;
    a.x *= c; a.y *= c; a.z *= c; a.w *= c;
    float ss2 = a.x * a.x + a.y * a.y + a.z * a.z + a.w * a.w;
#pragma unroll
    for (int o = 16; o > 0; o >>= 1) ss2 += __shfl_xor_sync(0xffffffffu, ss2, o);
    if ((threadIdx.x & 31) == 0) red[threadIdx.x >> 5] = ss2;
    __syncthreads();
    if (threadIdx.x == 0) {
        float t = 0.f;
#pragma unroll
        for (int i = 0; i < 8; i++) t += red[i];
        sval = rsqrtf(t * (1.0f / E_));
    }
    __syncthreads();
    float inv2 = sval;
    ((float4*)(x + (size_t)row * E_))[threadIdx.x] = a;
    ((uint2*)(h + (size_t)row * E_))[threadIdx.x] =
        make_uint2(h2u(__floats2half2_rn(a.x * inv2, a.y * inv2)),
                   h2u(__floats2half2_rn(a.z * inv2, a.w * inv2)));
}

// ---------------- geglu (fp16 in/out) ----------------
__global__ __launch_bounds__(256) void geglu_kernel(const __half* __restrict__ g,
                                                    const __half* __restrict__ v,
                                                    __half* __restrict__ o) {
    int i = (blockIdx.x * 256 + threadIdx.x) * 4;
    uint2 gu = *(const uint2*)(g + i);
    uint2 vu = *(const uint2*)(v + i);
    float2 g0 = __half22float2(*reinterpret_cast<__half2*>(&gu.x));
    float2 g1 = __half22float2(*reinterpret_cast<__half2*>(&gu.y));
    float2 v0 = __half22float2(*reinterpret_cast<__half2*>(&vu.x));
    float2 v1 = __half22float2(*reinterpret_cast<__half2*>(&vu.y));
    float r0 = 0.5f * g0.x * (1.0f + erff(g0.x * 0.70710678118654752f)) * v0.x;
    float r1 = 0.5f * g0.y * (1.0f + erff(g0.y * 0.70710678118654752f)) * v0.y;
    float r2 = 0.5f * g1.x * (1.0f + erff(g1.x * 0.70710678118654752f)) * v1.x;
    float r3 = 0.5f * g1.y * (1.0f + erff(g1.y * 0.70710678118654752f)) * v1.y;
    *(uint2*)(o + i) = make_uint2(h2u(__floats2half2_rn(r0, r1)),
                                  h2u(__floats2half2_rn(r2, r3)));
}

// ================= mma helpers =================
__device__ __forceinline__ void mma_f16(float* d, const uint32_t* a, const uint32_t* b) {
    asm volatile(
        "mma.sync.aligned.m16n8k16.row.col.f32.f16.f16.f32 "
        "{%0,%1,%2,%3}, {%4,%5,%6,%7}, {%8,%9}, {%0,%1,%2,%3};\n"
        : "+f"(d[0]), "+f"(d[1]), "+f"(d[2]), "+f"(d[3])
        : "r"(a[0]), "r"(a[1]), "r"(a[2]), "r"(a[3]), "r"(b[0]), "r"(b[1]));
}

__device__ __forceinline__ void ldsm4(uint32_t* r, uint32_t saddr) {
    asm volatile("ldmatrix.sync.aligned.m8n8.x4.shared.b16 {%0,%1,%2,%3}, [%4];"
                 : "=r"(r[0]), "=r"(r[1]), "=r"(r[2]), "=r"(r[3]) : "r"(saddr));
}
__device__ __forceinline__ void ldsm4t(uint32_t* r, uint32_t saddr) {
    asm volatile("ldmatrix.sync.aligned.m8n8.x4.trans.shared.b16 {%0,%1,%2,%3}, [%4];"
                 : "=r"(r[0]), "=r"(r[1]), "=r"(r[2]), "=r"(r[3]) : "r"(saddr));
}
__device__ __forceinline__ void ldsm2t(uint32_t* r, uint32_t saddr) {
    asm volatile("ldmatrix.sync.aligned.m8n8.x2.trans.shared.b16 {%0,%1}, [%2];"
                 : "=r"(r[0]), "=r"(r[1]) : "r"(saddr));
}
__device__ __forceinline__ void ldsm2(uint32_t* r, uint32_t saddr) {
    asm volatile("ldmatrix.sync.aligned.m8n8.x2.shared.b16 {%0,%1}, [%2];"
                 : "=r"(r[0]), "=r"(r[1]) : "r"(saddr));
}

// ================= fp16 tensor-core GEMM (R14, unchanged) =================
#define BM 64
#define BN 128
#define BK 64
#define ASTR 72
#define BSTR 136
#define ATILE_H (BM * ASTR)
#define BTILE_H (BK * BSTR)
#define STAGE_H (ATILE_H + BTILE_H)
#define TG_SMEM (2 * STAGE_H * 2)   // 53248 B

__global__ __launch_bounds__(256, 3) void hgemm_kernel(
    int M, int N, int K,
    const __half* __restrict__ A, const __half* __restrict__ B,
    const float* __restrict__ bias, const float* __restrict__ res,
    float* __restrict__ C, __half* __restrict__ C16,
    const __half* __restrict__ B2, float* __restrict__ C2, __half* __restrict__ C216) {
    extern __shared__ __half sm[];

    if (blockIdx.z) { B = B2; C = C2; C16 = C216; }

    const int tid  = threadIdx.x;
    const int bm   = blockIdx.y * BM;
    const int bn   = blockIdx.x * BN;
    const int warp = tid >> 5, lane = tid & 31;
    const int wm   = (warp >> 2) * 32;
    const int wn   = (warp & 3) * 32;
    const int fr   = lane >> 2;
    const int fc   = lane & 3;
    const int arow_l = ((lane >> 3) & 1) * 8 + (lane & 7);
    const int acol_l = ((lane >> 4) & 1) * 8;
    const int brow4_l = ((lane >> 3) & 1) * 8 + (lane & 7);
    const int bcol4_l = ((lane >> 4) & 1) * 8;

    float acc[2][4][4];
#pragma unroll
    for (int i = 0; i < 2; i++)
#pragma unroll
        for (int j = 0; j < 4; j++)
#pragma unroll
            for (int k = 0; k < 4; k++) acc[i][j][k] = 0.f;

    auto fill = [&](int s, int kt) {
        __half* Ad = sm + s * STAGE_H;
        __half* Bd = Ad + ATILE_H;
#pragma unroll
        for (int p = 0; p < 2; p++) {
            int idx = p * 256 + tid;
            int row = idx >> 3, c8 = idx & 7;
            uint32_t dst = (uint32_t)__cvta_generic_to_shared(Ad + row * ASTR + c8 * 8);
            const __half* src = A + (size_t)(bm + row) * K + kt + c8 * 8;
            asm volatile("cp.async.cg.shared.global [%0], [%1], 16;\n" :: "r"(dst), "l"(src));
        }
#pragma unroll
        for (int p = 0; p < 4; p++) {
            int idx = p * 256 + tid;
            int row = idx >> 4, c16 = idx & 15;
            uint32_t dst = (uint32_t)__cvta_generic_to_shared(Bd + row * BSTR + c16 * 8);
            const __half* src = B + (size_t)(kt + row) * N + bn + c16 * 8;
            asm volatile("cp.async.cg.shared.global [%0], [%1], 16;\n" :: "r"(dst), "l"(src));
        }
        asm volatile("cp.async.commit_group;\n");
    };

    auto compute_tile = [&](int s) {
        const __half* Ab = sm + s * STAGE_H;
        const __half* Bb = Ab + ATILE_H;
        uint32_t abase = (uint32_t)__cvta_generic_to_shared(Ab + (wm + arow_l) * ASTR + acol_l);
        uint32_t bbase = (uint32_t)__cvta_generic_to_shared(Bb + brow4_l * BSTR + wn + bcol4_l);
#pragma unroll
        for (int ks = 0; ks < 4; ks++) {
            uint32_t af[2][4], bf[4][2];
#pragma unroll
            for (int mi = 0; mi < 2; mi++)
                ldsm4(af[mi], abase + (mi * 16 * ASTR + ks * 16) * 2);
#pragma unroll
            for (int n2 = 0; n2 < 2; n2++) {
                uint32_t r4[4];
                ldsm4t(r4, bbase + (ks * 16 * BSTR + n2 * 16) * 2);
                bf[2 * n2][0] = r4[0]; bf[2 * n2][1] = r4[1];
                bf[2 * n2 + 1][0] = r4[2]; bf[2 * n2 + 1][1] = r4[3];
            }
#pragma unroll
            for (int mi = 0; mi < 2; mi++)
#pragma unroll
                for (int ni = 0; ni < 4; ni++) mma_f16(acc[mi][ni], af[mi], bf[ni]);
        }
    };

    const int kiters = K / BK;
    fill(0, 0);
    asm volatile("cp.async.wait_group 0;\n");
    __syncthreads();

#pragma unroll 1
    for (int it = 0; it < kiters; ++it) {
        int cur = it & 1;
        if (it + 1 < kiters) fill(cur ^ 1, (it + 1) * BK);
        compute_tile(cur);
        asm volatile("cp.async.wait_group 0;\n");
        __syncthreads();
    }

#pragma unroll
    for (int mi = 0; mi < 2; mi++) {
#pragma unroll
        for (int ni = 0; ni < 4; ni++) {
            int gr = bm + wm + mi * 16 + fr;
            int gc = bn + wn + ni * 8 + fc * 2;
            float2 o0 = make_float2(acc[mi][ni][0], acc[mi][ni][1]);
            float2 o1 = make_float2(acc[mi][ni][2], acc[mi][ni][3]);
            if (bias) {
                float2 bv = *(const float2*)(bias + gc);
                o0.x += bv.x; o0.y += bv.y;
                o1.x += bv.x; o1.y += bv.y;
            }
            if (res) {
                float2 r0 = *(const float2*)(res + (size_t)gr * N + gc);
                float2 r1 = *(const float2*)(res + (size_t)(gr + 8) * N + gc);
                o0.x += r0.x; o0.y += r0.y;
                o1.x += r1.x; o1.y += r1.y;
            }
            if (C16) {
                *(__half2*)(C16 + (size_t)gr * N + gc) = __floats2half2_rn(o0.x, o0.y);
                *(__half2*)(C16 + (size_t)(gr + 8) * N + gc) = __floats2half2_rn(o1.x, o1.y);
            } else {
                *(float2*)(C + (size_t)gr * N + gc) = o0;
                *(float2*)(C + (size_t)(gr + 8) * N + gc) = o1;
            }
        }
    }
}

// ================= fp16 flash attention: 3-deep KV ring reusing dead Q smem =================
// After qf is register-loaded, Qs (4608 halves = one K tile) is dead -> it becomes K of
// ring slot 2. Layout (halves): [K2=Qs:0 | K0:4608 | V0:9216 | K1:13824 | V1:18432 | V2:23040]
// Total 27648 halves = 55296 B -> 4 CTAs/SM (same as R15). Single barrier per tile.
#define ATSTR 72
#define KTILE 4608
#define ATT_SMEM (6 * KTILE * 2)   // 55296 B

__global__ __launch_bounds__(128) void attn_kernel(const __half* __restrict__ qkv,
                                                   __half* __restrict__ ctx) {
    extern __shared__ __half smh[];

    const int qt = (int)(gridDim.x - 1 - blockIdx.x);   // longest rows first
    const int h = blockIdx.y, b = blockIdx.z;
    const int m0 = qt * 64;
    const int tid  = threadIdx.x;
    const int warp = tid >> 5, lane = tid & 31;
    const int fr = lane >> 2, fc = lane & 3;
    const int w16 = warp * 16;
    const int arow_l = ((lane >> 3) & 1) * 8 + (lane & 7);
    const int acol_l = ((lane >> 4) & 1) * 8;
    const int brow_l = arow_l;
    const int krow_l = lane & 7;
    const int ksel_l = ((lane >> 3) & 1) * 8;
    const float LOG2E = 1.44269504088896341f;
    const float slope2 = exp2f(-(1.0f + 7.0f * (float)h / 15.0f)) * LOG2E;
    const float step8 = 8.0f * slope2;
    const __half2 qscale = __floats2half2_rn(0.125f * LOG2E, 0.125f * LOG2E);

    auto kofs = [](int s) -> int { return (s == 0) ? KTILE : (s == 1) ? 3 * KTILE : 0; };
    auto vofs = [](int s) -> int { return (s == 0) ? 2 * KTILE : (s == 1) ? 4 * KTILE : 5 * KTILE; };

    auto fill_kv = [&](int kt) {
        int s = kt % 3;
        __half* Kd = smh + kofs(s);
        __half* Vd = smh + vofs(s);
        const int n0 = kt * 64;
#pragma unroll
        for (int p = 0; p < 4; p++) {
            int i = p * 128 + tid;
            int r = i >> 3, c = (i & 7) * 8;
            size_t base = ((size_t)(b * L_ + n0 + r) * H_ + h) * 3;
            uint32_t kd = (uint32_t)__cvta_generic_to_shared(Kd + r * ATSTR + c);
            uint32_t vd = (uint32_t)__cvta_generic_to_shared(Vd + r * ATSTR + c);
            const __half* ks = qkv + (base + 1) * D_ + c;
            const __half* vs = qkv + (base + 2) * D_ + c;
            asm volatile("cp.async.cg.shared.global [%0], [%1], 16;\n" :: "r"(kd), "l"(ks));
            asm volatile("cp.async.cg.shared.global [%0], [%1], 16;\n" :: "r"(vd), "l"(vs));
        }
        asm volatile("cp.async.commit_group;\n");
    };

    // ---- Q tile into slot-2 K region (temporarily) ----
    __half* Qs = smh;   // == K2 region; dead after qf load
    for (int i = tid; i < 64 * 16; i += 128) {
        int r = i >> 4, c = (i & 15) << 2;
        uint2 v = *(const uint2*)(qkv + ((((size_t)(b * L_ + m0 + r) * H_ + h) * 3 + 0) * D_ + c));
        __half2 q0 = __hmul2(*reinterpret_cast<__half2*>(&v.x), qscale);
        __half2 q1 = __hmul2(*reinterpret_cast<__half2*>(&v.y), qscale);
        *(uint2*)(Qs + r * ATSTR + c) = make_uint2(h2u(q0), h2u(q1));
    }
    fill_kv(0);
    if (qt >= 1) fill_kv(1);
    __syncthreads();

    const uint32_t qbase = (uint32_t)__cvta_generic_to_shared(Qs + (w16 + arow_l) * ATSTR + acol_l);
    uint32_t qf[4][4];
#pragma unroll
    for (int ks = 0; ks < 4; ks++) ldsm4(qf[ks], qbase + ks * 16 * 2);
    // Qs region is now dead; first overwrite (fill_kv(2)) is issued after the
    // kt=0 top barrier, which orders it after every warp's qf loads.

    float oacc[8][4];
#pragma unroll
    for (int i = 0; i < 8; i++)
#pragma unroll
        for (int j = 0; j < 4; j++) oacc[i][j] = 0.f;
    float mrow0 = -CUDART_INF_F, mrow1 = -CUDART_INF_F;
    float lrow0 = 0.f, lrow1 = 0.f;

    const int gi0 = m0 + w16 + fr;
    const int gi1 = gi0 + 8;

#pragma unroll 1
    for (int kt = 0; kt <= qt; kt++) {
        const int n0 = kt * 64;
        if (kt < qt) asm volatile("cp.async.wait_group 1;\n");
        else         asm volatile("cp.async.wait_group 0;\n");
        __syncthreads();   // fill kt visible; prior reads of slot (kt+2)%3 fenced
        if (kt + 2 <= qt) fill_kv(kt + 2);

        int s = kt % 3;
        const __half* Kd = smh + kofs(s);
        const __half* Vd = smh + vofs(s);
        const uint32_t kbase = (uint32_t)__cvta_generic_to_shared(Kd + krow_l * ATSTR + ksel_l);
        const uint32_t vbase = (uint32_t)__cvta_generic_to_shared(Vd + brow_l * ATSTR);

        float sacc[8][4];
#pragma unroll
        for (int i = 0; i < 8; i++)
#pragma unroll
            for (int j = 0; j < 4; j++) sacc[i][j] = 0.f;
#pragma unroll
        for (int ks = 0; ks < 4; ks++) {
            uint32_t bf[8][2];
#pragma unroll
            for (int ni = 0; ni < 8; ni++)
                ldsm2(bf[ni], kbase + (ni * 8 * ATSTR + ks * 16) * 2);
#pragma unroll
            for (int ni = 0; ni < 8; ni++) mma_f16(sacc[ni], qf[ks], bf[ni]);
        }

        {
            float a0 = slope2 * (float)(n0 + 2 * fc - gi0);
            float a2 = slope2 * (float)(n0 + 2 * fc - gi1);
            if (kt < qt) {
#pragma unroll
                for (int ni = 0; ni < 8; ni++) {
                    sacc[ni][0] += a0;
                    sacc[ni][1] += a0 + slope2;
                    sacc[ni][2] += a2;
                    sacc[ni][3] += a2 + slope2;
                    a0 += step8;
                    a2 += step8;
                }
            } else {
#pragma unroll
                for (int ni = 0; ni < 8; ni++) {
                    int gj = n0 + ni * 8 + 2 * fc;
                    sacc[ni][0] = (gj     > gi0) ? -CUDART_INF_F : sacc[ni][0] + a0;
                    sacc[ni][1] = (gj + 1 > gi0) ? -CUDART_INF_F : sacc[ni][1] + a0 + slope2;
                    sacc[ni][2] = (gj     > gi1) ? -CUDART_INF_F : sacc[ni][2] + a2;
                    sacc[ni][3] = (gj + 1 > gi1) ? -CUDART_INF_F : sacc[ni][3] + a2 + slope2;
                    a0 += step8;
                    a2 += step8;
                }
            }
        }

        float mx0 = -CUDART_INF_F, mx1 = -CUDART_INF_F;
#pragma unroll
        for (int ni = 0; ni < 8; ni++) {
            mx0 = fmaxf(mx0, fmaxf(sacc[ni][0], sacc[ni][1]));
            mx1 = fmaxf(mx1, fmaxf(sacc[ni][2], sacc[ni][3]));
        }
        mx0 = fmaxf(mx0, __shfl_xor_sync(0xffffffffu, mx0, 1));
        mx0 = fmaxf(mx0, __shfl_xor_sync(0xffffffffu, mx0, 2));
        mx1 = fmaxf(mx1, __shfl_xor_sync(0xffffffffu, mx1, 1));
        mx1 = fmaxf(mx1, __shfl_xor_sync(0xffffffffu, mx1, 2));
        float mn0 = fmaxf(mrow0, mx0);
        float mn1 = fmaxf(mrow1, mx1);
        float alpha0 = exp2f(mrow0 - mn0);
        float alpha1 = exp2f(mrow1 - mn1);
        float rs0 = 0.f, rs1 = 0.f;
#pragma unroll
        for (int ni = 0; ni < 8; ni++) {
            sacc[ni][0] = exp2f(sacc[ni][0] - mn0);
            sacc[ni][1] = exp2f(sacc[ni][1] - mn0);
            sacc[ni][2] = exp2f(sacc[ni][2] - mn1);
            sacc[ni][3] = exp2f(sacc[ni][3] - mn1);
            rs0 += sacc[ni][0] + sacc[ni][1];
            rs1 += sacc[ni][2] + sacc[ni][3];
        }
        rs0 += __shfl_xor_sync(0xffffffffu, rs0, 1);
        rs0 += __shfl_xor_sync(0xffffffffu, rs0, 2);
        rs1 += __shfl_xor_sync(0xffffffffu, rs1, 1);
        rs1 += __shfl_xor_sync(0xffffffffu, rs1, 2);
        lrow0 = lrow0 * alpha0 + rs0;
        lrow1 = lrow1 * alpha1 + rs1;
        mrow0 = mn0;
        mrow1 = mn1;
#pragma unroll
        for (int ni = 0; ni < 8; ni++) {
            oacc[ni][0] *= alpha0;
            oacc[ni][1] *= alpha0;
            oacc[ni][2] *= alpha1;
            oacc[ni][3] *= alpha1;
        }

#pragma unroll
        for (int ks = 0; ks < 4; ks++) {
            uint32_t af[4];
            af[0] = h2u(__floats2half2_rn(sacc[2 * ks][0],     sacc[2 * ks][1]));
            af[1] = h2u(__floats2half2_rn(sacc[2 * ks][2],     sacc[2 * ks][3]));
            af[2] = h2u(__floats2half2_rn(sacc[2 * ks + 1][0], sacc[2 * ks + 1][1]));
            af[3] = h2u(__floats2half2_rn(sacc[2 * ks + 1][2], sacc[2 * ks + 1][3]));
#pragma unroll
            for (int ni = 0; ni < 8; ni++) {
                uint32_t bf[2];
                ldsm2t(bf, vbase + (ks * 16 * ATSTR + ni * 8) * 2);
                mma_f16(oacc[ni], af, bf);
            }
        }
        // no bottom barrier: next iteration's top barrier fences slot reuse
    }

    float inv0 = 1.0f / lrow0;
    float inv1 = 1.0f / lrow1;
#pragma unroll
    for (int ni = 0; ni < 8; ni++) {
        int c = h * D_ + ni * 8 + 2 * fc;
        *(__half2*)(ctx + (size_t)(b * L_ + gi0) * HD_ + c) =
            __floats2half2_rn(oacc[ni][0] * inv0, oacc[ni][1] * inv0);
        *(__half2*)(ctx + (size_t)(b * L_ + gi1) * HD_ + c) =
            __floats2half2_rn(oacc[ni][2] * inv1, oacc[ni][3] * inv1);
    }
}

// ---------------- launch ----------------
extern "C" void kernel_launch(void* const* d_in, const int* in_sizes, int n_in,
                              void* d_out, int out_size) {
    (void)in_sizes; (void)n_in; (void)out_size;
    const float* X    = (const float*)d_in[0];
    const float* Wqkv = (const float*)d_in[2];
    const float* bqkv = (const float*)d_in[3];
    const float* Wo   = (const float*)d_in[4];
    const float* bo   = (const float*)d_in[5];
    const float* Ww   = (const float*)d_in[12];
    const float* Wv   = (const float*)d_in[13];
    const float* Wout = (const float*)d_in[14];
    float* out = (float*)d_out;

    float *x_p;
    __half *h16, *qkv16, *ctx16, *gate16, *val16, *gg16;
    __half *wqkv16, *wo16, *ww16, *wv16, *wout16;
    cudaGetSymbolAddress((void**)&x_p,    g_x);
    cudaGetSymbolAddress((void**)&h16,    g_h16);
    cudaGetSymbolAddress((void**)&qkv16,  g_qkv16);
    cudaGetSymbolAddress((void**)&ctx16,  g_ctx16);
    cudaGetSymbolAddress((void**)&gate16, g_gate16);
    cudaGetSymbolAddress((void**)&val16,  g_val16);
    cudaGetSymbolAddress((void**)&gg16,   g_gg16);
    cudaGetSymbolAddress((void**)&wqkv16, g_wqkv16);
    cudaGetSymbolAddress((void**)&wo16,   g_wo16);
    cudaGetSymbolAddress((void**)&ww16,   g_ww16);
    cudaGetSymbolAddress((void**)&wv16,   g_wv16);
    cudaGetSymbolAddress((void**)&wout16, g_wout16);

    cudaFuncSetAttribute(attn_kernel, cudaFuncAttributeMaxDynamicSharedMemorySize, ATT_SMEM);
    cudaFuncSetAttribute(hgemm_kernel, cudaFuncAttributeMaxDynamicSharedMemorySize, TG_SMEM);

    // 0. all fp16 weight conversions in one launch
    f2h_all_kernel<<<16384, 256>>>(Wqkv, wqkv16, Wo, wo16, Ww, ww16, Wv, wv16, Wout, wout16);

    // 1. h16 = rmsnorm(X)
    rmsnorm_kernel<<<M_, 256>>>(X, h16);
    // 2. qkv16 = h16 @ wqkv16 + bqkv
    hgemm_kernel<<<dim3(3 * HD_ / BN, M_ / BM), 256, TG_SMEM>>>(
        M_, 3 * HD_, E_, h16, wqkv16, bqkv, nullptr, nullptr, qkv16,
        nullptr, nullptr, nullptr);
    // 3. attention
    attn_kernel<<<dim3(L_ / 64, H_, B_), 128, ATT_SMEM>>>(qkv16, ctx16);
    // 4. x = X + ctx16 @ wo16 + bo
    hgemm_kernel<<<dim3(E_ / BN, M_ / BM), 256, TG_SMEM>>>(
        M_, E_, HD_, ctx16, wo16, bo, X, x_p, nullptr,
        nullptr, nullptr, nullptr);
    // 5+6. x = x + rmsnorm(x); h16 = rmsnorm(x)
    addnorm_kernel<<<M_, 256>>>(x_p, h16);
    // 7. gate16 / val16 (dual-output, z selects)
    hgemm_kernel<<<dim3(DFF_ / BN, M_ / BM, 2), 256, TG_SMEM>>>(
        M_, DFF_, E_, h16, ww16, nullptr, nullptr, nullptr, gate16,
        wv16, nullptr, val16);
    // 8. gg16 = gelu(gate16) * val16
    geglu_kernel<<<(M_ * DFF_) / 1024, 256>>>(gate16, val16, gg16);
    // 9. out = x + gg16 @ wout16
    hgemm_kernel<<<dim3(E_ / BN, M_ / BM), 256, TG_SMEM>>>(
        M_, E_, DFF_, gg16, wout16, nullptr, x_p, out, nullptr,
        nullptr, nullptr, nullptr);
}